// round 5
// baseline (speedup 1.0000x reference)
#include <cuda_runtime.h>

#define B_  4
#define S_  2048
#define DM_ 512
#define H_  8
#define D_  64
#define MROWS (B_*S_)     // 8192
#define QT 32
#define NKPAD 292         // 288 band keys max, padded

// Scratch (allocation-free contract: __device__ globals)
__device__ float g_q[MROWS*DM_];
__device__ float g_k[MROWS*DM_];
__device__ float g_v[MROWS*DM_];
__device__ float g_ctx[MROWS*DM_];
__device__ float g_vmean[B_*DM_];

// ---------------------------------------------------------------------------
// SGEMM: C[M,N] = A[M,K] @ W[K,N] + bias[N]; M=8192, N=K=512 fixed.
// 128x128 block tile, 8x8 per-thread microtile, K-step 8.
// ---------------------------------------------------------------------------
__global__ __launch_bounds__(256, 2)
void sgemm_bias(const float* __restrict__ A, const float* __restrict__ W,
                const float* __restrict__ bias, float* __restrict__ C)
{
    const int N = DM_, K = DM_;
    __shared__ float As[8][128];
    __shared__ float Bs[8][128];

    const int bm = blockIdx.y * 128, bn = blockIdx.x * 128;
    const int tid = threadIdx.x;
    const int tx = tid & 15, ty = tid >> 4;
    const int arow = tid >> 1, acol = (tid & 1) * 4;
    const int brow = tid >> 5, bcol = (tid & 31) * 4;

    const float* Ap = A + (size_t)(bm + arow) * K + acol;
    const float* Wp = W + (size_t)brow * N + bn + bcol;

    float acc[8][8];
    #pragma unroll
    for (int i = 0; i < 8; i++)
        #pragma unroll
        for (int j = 0; j < 8; j++) acc[i][j] = 0.0f;

    for (int k0 = 0; k0 < K; k0 += 8) {
        float4 a4 = *(const float4*)(Ap + k0);
        float4 b4 = *(const float4*)(Wp + (size_t)k0 * N);
        __syncthreads();
        As[acol + 0][arow] = a4.x;
        As[acol + 1][arow] = a4.y;
        As[acol + 2][arow] = a4.z;
        As[acol + 3][arow] = a4.w;
        *(float4*)&Bs[brow][bcol] = b4;
        __syncthreads();
        #pragma unroll
        for (int kk = 0; kk < 8; kk++) {
            float4 a0 = *(const float4*)&As[kk][ty * 4];
            float4 a1 = *(const float4*)&As[kk][64 + ty * 4];
            float4 b0 = *(const float4*)&Bs[kk][tx * 4];
            float4 b1 = *(const float4*)&Bs[kk][64 + tx * 4];
            float av[8] = {a0.x, a0.y, a0.z, a0.w, a1.x, a1.y, a1.z, a1.w};
            float bv[8] = {b0.x, b0.y, b0.z, b0.w, b1.x, b1.y, b1.z, b1.w};
            #pragma unroll
            for (int i = 0; i < 8; i++)
                #pragma unroll
                for (int j = 0; j < 8; j++)
                    acc[i][j] += av[i] * bv[j];
        }
    }

    #pragma unroll
    for (int i = 0; i < 8; i++) {
        int row = bm + ((i < 4) ? (ty * 4 + i) : (64 + ty * 4 + i - 4));
        #pragma unroll
        for (int jh = 0; jh < 2; jh++) {
            int col = bn + jh * 64 + tx * 4;
            float4 o;
            o.x = acc[i][jh * 4 + 0] + bias[col + 0];
            o.y = acc[i][jh * 4 + 1] + bias[col + 1];
            o.z = acc[i][jh * 4 + 2] + bias[col + 2];
            o.w = acc[i][jh * 4 + 3] + bias[col + 3];
            *(float4*)&C[(size_t)row * N + col] = o;
        }
    }
}

// ---------------------------------------------------------------------------
// vmean[b, c] = mean_j v[b, j, c]  (fallback for fully-masked softmax rows)
// ---------------------------------------------------------------------------
__global__ void vmean_kernel()
{
    int idx = blockIdx.x * blockDim.x + threadIdx.x;   // 0..2047
    int b = idx >> 9;
    int c = idx & 511;
    const float* p = g_v + (size_t)b * S_ * DM_ + c;
    float s0 = 0.f, s1 = 0.f, s2 = 0.f, s3 = 0.f;
    for (int j = 0; j < S_; j += 4) {
        s0 += p[(size_t)(j + 0) * DM_];
        s1 += p[(size_t)(j + 1) * DM_];
        s2 += p[(size_t)(j + 2) * DM_];
        s3 += p[(size_t)(j + 3) * DM_];
    }
    g_vmean[idx] = (s0 + s1 + s2 + s3) * (1.0f / S_);
}

// ---------------------------------------------------------------------------
// Banded attention. Block = (query-tile of 32, head, batch). 256 threads.
// Smem: Q tile [32][68], K/V chunk [32][68], scores [32][NKPAD], row stats.
// ---------------------------------------------------------------------------
__global__ __launch_bounds__(256)
void attn_kernel(const int* __restrict__ x_len)
{
    extern __shared__ float sm[];
    float* Qs      = sm;                 // 32*68
    float* KVs     = Qs  + 32 * 68;      // 32*68
    float* Ss      = KVs + 32 * 68;      // 32*NKPAD
    float* rowinv  = Ss  + 32 * NKPAD;   // 32
    float* rowflag = rowinv + 32;        // 32

    const int qt = blockIdx.x, h = blockIdx.y, b = blockIdx.z;
    const int i0 = qt * QT;
    const int kbeg = max(0, i0 - 128);
    const int kend = min(S_, i0 + QT + 128);
    const int nk = kend - kbeg;
    const int nch = (nk + 31) >> 5;
    const int xlen = x_len[b];
    const int tid = threadIdx.x;

    const int qi   = tid >> 3;
    const int dblk = (tid & 7) * 8;

    // Load Q tile
    {
        const float* src = g_q + ((size_t)(b * S_ + i0 + qi)) * DM_ + h * D_ + dblk;
        *(float4*)&Qs[qi * 68 + dblk]     = *(const float4*)src;
        *(float4*)&Qs[qi * 68 + dblk + 4] = *(const float4*)(src + 4);
    }

    const int ty = tid >> 4, tx = tid & 15;

    // --- Scores: S[32 x nch*32], masked, scaled by 1/sqrt(64) ---
    for (int c = 0; c < nch; c++) {
        int jb = kbeg + c * 32;
        __syncthreads();
        {
            int j = jb + qi;
            float4 x0 = make_float4(0.f, 0.f, 0.f, 0.f), x1 = x0;
            if (j < kend) {
                const float* src = g_k + ((size_t)(b * S_ + j)) * DM_ + h * D_ + dblk;
                x0 = *(const float4*)src;
                x1 = *(const float4*)(src + 4);
            }
            *(float4*)&KVs[qi * 68 + dblk]     = x0;
            *(float4*)&KVs[qi * 68 + dblk + 4] = x1;
        }
        __syncthreads();

        float s00 = 0.f, s01 = 0.f, s10 = 0.f, s11 = 0.f;
        #pragma unroll
        for (int cc = 0; cc < 16; cc++) {
            float4 qa = *(const float4*)&Qs[(2 * ty + 0) * 68 + cc * 4];
            float4 qb = *(const float4*)&Qs[(2 * ty + 1) * 68 + cc * 4];
            float4 ka = *(const float4*)&KVs[(2 * tx + 0) * 68 + cc * 4];
            float4 kb = *(const float4*)&KVs[(2 * tx + 1) * 68 + cc * 4];
            s00 += qa.x * ka.x + qa.y * ka.y + qa.z * ka.z + qa.w * ka.w;
            s01 += qa.x * kb.x + qa.y * kb.y + qa.z * kb.z + qa.w * kb.w;
            s10 += qb.x * ka.x + qb.y * ka.y + qb.z * ka.z + qb.w * ka.w;
            s11 += qb.x * kb.x + qb.y * kb.y + qb.z * kb.z + qb.w * kb.w;
        }
        float sv[2][2] = {{s00, s01}, {s10, s11}};
        #pragma unroll
        for (int qq = 0; qq < 2; qq++) {
            #pragma unroll
            for (int kk = 0; kk < 2; kk++) {
                int i = i0 + 2 * ty + qq;
                int j = jb + 2 * tx + kk;
                bool valid = (j - i <= 128) && (i - j <= 128) && (j < xlen) && (j < kend);
                Ss[(2 * ty + qq) * NKPAD + c * 32 + 2 * tx + kk] =
                    valid ? sv[qq][kk] * 0.125f : -1e30f;
            }
        }
    }
    __syncthreads();

    // --- Softmax over nch*32 written columns; warp w handles rows w, w+8, ... ---
    const int wid = tid >> 5, lane = tid & 31;
    const int nkr = nch * 32;
    for (int rr = 0; rr < 4; rr++) {
        int r = wid + rr * 8;
        float m = -3e38f;
        for (int c = lane; c < nkr; c += 32) m = fmaxf(m, Ss[r * NKPAD + c]);
        #pragma unroll
        for (int o = 16; o; o >>= 1) m = fmaxf(m, __shfl_xor_sync(0xffffffffu, m, o));
        float sum = 0.f;
        for (int c = lane; c < nkr; c += 32) {
            float p = __expf(Ss[r * NKPAD + c] - m);
            Ss[r * NKPAD + c] = p;
            sum += p;
        }
        #pragma unroll
        for (int o = 16; o; o >>= 1) sum += __shfl_xor_sync(0xffffffffu, sum, o);
        if (lane == 0) {
            rowinv[r]  = 1.0f / sum;
            rowflag[r] = (m <= -1e29f) ? 1.0f : 0.0f;  // fully masked row
        }
    }

    // --- O = P @ V ---
    float acc[8] = {0.f, 0.f, 0.f, 0.f, 0.f, 0.f, 0.f, 0.f};
    for (int c = 0; c < nch; c++) {
        int jb = kbeg + c * 32;
        __syncthreads();
        {
            int j = jb + qi;
            float4 x0 = make_float4(0.f, 0.f, 0.f, 0.f), x1 = x0;
            if (j < kend) {
                const float* src = g_v + ((size_t)(b * S_ + j)) * DM_ + h * D_ + dblk;
                x0 = *(const float4*)src;
                x1 = *(const float4*)(src + 4);
            }
            *(float4*)&KVs[qi * 68 + dblk]     = x0;
            *(float4*)&KVs[qi * 68 + dblk + 4] = x1;
        }
        __syncthreads();
        #pragma unroll
        for (int j4 = 0; j4 < 8; j4++) {
            float4 p4 = *(const float4*)&Ss[qi * NKPAD + c * 32 + j4 * 4];
            float pv[4] = {p4.x, p4.y, p4.z, p4.w};
            #pragma unroll
            for (int t = 0; t < 4; t++) {
                int j = j4 * 4 + t;
                float4 v0 = *(const float4*)&KVs[j * 68 + dblk];
                float4 v1 = *(const float4*)&KVs[j * 68 + dblk + 4];
                acc[0] += pv[t] * v0.x; acc[1] += pv[t] * v0.y;
                acc[2] += pv[t] * v0.z; acc[3] += pv[t] * v0.w;
                acc[4] += pv[t] * v1.x; acc[5] += pv[t] * v1.y;
                acc[6] += pv[t] * v1.z; acc[7] += pv[t] * v1.w;
            }
        }
    }

    float inv  = rowinv[qi];
    bool  flag = rowflag[qi] > 0.5f;
    float* dst = g_ctx + ((size_t)(b * S_ + i0 + qi)) * DM_ + h * D_ + dblk;
    const float* vm = g_vmean + b * DM_ + h * D_ + dblk;
    float4 o0, o1;
    o0.x = flag ? vm[0] : acc[0] * inv;
    o0.y = flag ? vm[1] : acc[1] * inv;
    o0.z = flag ? vm[2] : acc[2] * inv;
    o0.w = flag ? vm[3] : acc[3] * inv;
    o1.x = flag ? vm[4] : acc[4] * inv;
    o1.y = flag ? vm[5] : acc[5] * inv;
    o1.z = flag ? vm[6] : acc[6] * inv;
    o1.w = flag ? vm[7] : acc[7] * inv;
    *(float4*)dst       = o0;
    *(float4*)(dst + 4) = o1;
}

// ---------------------------------------------------------------------------
extern "C" void kernel_launch(void* const* d_in, const int* in_sizes, int n_in,
                              void* d_out, int out_size)
{
    (void)in_sizes; (void)n_in; (void)out_size;
    const float* x  = (const float*)d_in[0];
    const float* Wq = (const float*)d_in[1];
    const float* bq = (const float*)d_in[2];
    const float* Wk = (const float*)d_in[3];
    const float* bk = (const float*)d_in[4];
    const float* Wv = (const float*)d_in[5];
    const float* bv = (const float*)d_in[6];
    const float* Wo = (const float*)d_in[7];
    const float* bo = (const float*)d_in[8];
    const int*   xl = (const int*)d_in[9];
    float* out = (float*)d_out;

    float *gq, *gk, *gv, *gctx;
    cudaGetSymbolAddress((void**)&gq,   g_q);
    cudaGetSymbolAddress((void**)&gk,   g_k);
    cudaGetSymbolAddress((void**)&gv,   g_v);
    cudaGetSymbolAddress((void**)&gctx, g_ctx);

    dim3 ggrid(DM_ / 128, MROWS / 128);   // (4, 64)
    sgemm_bias<<<ggrid, 256>>>(x, Wq, bq, gq);
    sgemm_bias<<<ggrid, 256>>>(x, Wk, bk, gk);
    sgemm_bias<<<ggrid, 256>>>(x, Wv, bv, gv);

    vmean_kernel<<<8, 256>>>();

    const int smem_bytes = (32 * 68 * 2 + 32 * NKPAD + 64) * sizeof(float);  // ~55KB
    cudaFuncSetAttribute(attn_kernel, cudaFuncAttributeMaxDynamicSharedMemorySize,
                         smem_bytes);
    attn_kernel<<<dim3(S_ / QT, H_, B_), 256, smem_bytes>>>(xl);

    sgemm_bias<<<ggrid, 256>>>(gctx, Wo, bo, out);
}

// round 8
// speedup vs baseline: 1.3966x; 1.3966x over previous
#include <cuda_runtime.h>
#include <cuda_bf16.h>
#include <cstdint>

#define B_  4
#define S_  2048
#define DM_ 512
#define H_  8
#define D_  64
#define MROWS (B_*S_)     // 8192
#define QT 32
#define NKPAD 292

// ---------------- scratch (__device__ globals, allocation-free) ----------------
__device__ float g_q[MROWS*DM_];
__device__ float g_k[MROWS*DM_];
__device__ float g_v[MROWS*DM_];
__device__ float g_ctx[MROWS*DM_];
__device__ float g_vmean[B_*DM_];

__device__ __nv_bfloat16 g_ah[MROWS*DM_];   // A hi (x, later ctx)
__device__ __nv_bfloat16 g_al[MROWS*DM_];   // A lo
__device__ __nv_bfloat16 g_wth[4][DM_*DM_]; // W^T hi (q,k,v,o)
__device__ __nv_bfloat16 g_wtl[4][DM_*DM_]; // W^T lo

// ---------------- helpers ----------------
__device__ __forceinline__ uint32_t smem_u32(const void* p) {
    uint32_t a;
    asm("{ .reg .u64 t; cvta.to.shared.u64 t, %1; cvt.u32.u64 %0, t; }" : "=r"(a) : "l"(p));
    return a;
}
__device__ __forceinline__ void cp16(uint32_t dst, const void* src) {
    asm volatile("cp.async.cg.shared.global [%0], [%1], 16;" :: "r"(dst), "l"(src) : "memory");
}
#define CP_COMMIT() asm volatile("cp.async.commit_group;" ::: "memory")

__device__ __forceinline__ void ldsm4(uint32_t* r, uint32_t addr) {
    asm volatile("ldmatrix.sync.aligned.m8n8.x4.shared.b16 {%0,%1,%2,%3}, [%4];"
                 : "=r"(r[0]), "=r"(r[1]), "=r"(r[2]), "=r"(r[3]) : "r"(addr));
}
__device__ __forceinline__ void mma16816(float* c, const uint32_t* a, const uint32_t* b) {
    asm volatile(
        "mma.sync.aligned.m16n8k16.row.col.f32.bf16.bf16.f32 "
        "{%0,%1,%2,%3}, {%4,%5,%6,%7}, {%8,%9}, {%0,%1,%2,%3};"
        : "+f"(c[0]), "+f"(c[1]), "+f"(c[2]), "+f"(c[3])
        : "r"(a[0]), "r"(a[1]), "r"(a[2]), "r"(a[3]), "r"(b[0]), "r"(b[1]));
}

// ---------------------------------------------------------------------------
// prep: split fp32 -> bf16 hi/lo
// ---------------------------------------------------------------------------
__global__ void prep_split(const float* __restrict__ src,
                           __nv_bfloat16* __restrict__ hi,
                           __nv_bfloat16* __restrict__ lo, int n)
{
    int i = blockIdx.x * blockDim.x + threadIdx.x;
    for (; i < n; i += gridDim.x * blockDim.x) {
        float v = src[i];
        __nv_bfloat16 h = __float2bfloat16(v);
        hi[i] = h;
        lo[i] = __float2bfloat16(v - __bfloat162float(h));
    }
}

// transpose + split W[512,512] -> Wt[n][k] hi/lo
__global__ void prep_wt(const float* __restrict__ W,
                        __nv_bfloat16* __restrict__ th,
                        __nv_bfloat16* __restrict__ tl)
{
    __shared__ float t[32][33];
    int bk = blockIdx.x * 32, bn = blockIdx.y * 32;
    int tx = threadIdx.x, ty = threadIdx.y;   // 32 x 8
    #pragma unroll
    for (int i = 0; i < 32; i += 8)
        t[ty + i][tx] = W[(size_t)(bk + ty + i) * DM_ + bn + tx];
    __syncthreads();
    #pragma unroll
    for (int i = 0; i < 32; i += 8) {
        float v = t[tx][ty + i];
        __nv_bfloat16 h = __float2bfloat16(v);
        size_t o = (size_t)(bn + ty + i) * DM_ + bk + tx;
        th[o] = h;
        tl[o] = __float2bfloat16(v - __bfloat162float(h));
    }
}

// ---------------------------------------------------------------------------
// HMMA split-bf16 GEMM: C[8192,512] = A*W + bias (fp32-accurate).
// CTA 128x128, 8 warps (4x2 -> 32x64 warp tiles), K chunk 64, cp.async 2-buf.
// Smem rows: 64 bf16 data padded to 72 (144B stride => conflict-free ldmatrix).
// ---------------------------------------------------------------------------
#define SROWB 144                  // bytes per smem row (72 bf16)
#define TILEB (128 * SROWB)        // 18432 B per 128x64 tile
#define OFF_AH 0
#define OFF_AL (TILEB)
#define OFF_BH (2 * TILEB)
#define OFF_BL (3 * TILEB)
#define BUFB   (4 * TILEB)         // 73728 B per buffer
#define GSMEM_TOT (2 * BUFB)       // 147456 B

__device__ __forceinline__ void load_chunk(uint32_t dst, const __nv_bfloat16* g, int tid)
{
    // 128 rows x 128B (64 bf16); global row stride 512 bf16 = 1024B
    #pragma unroll
    for (int it = 0; it < 4; it++) {
        int idx = tid + it * 256;
        int r = idx >> 3, c = idx & 7;
        cp16(dst + r * SROWB + c * 16, (const char*)g + (size_t)r * 1024 + c * 16);
    }
}

__global__ __launch_bounds__(256, 1)
void gemm_tc(const __nv_bfloat16* __restrict__ Ah, const __nv_bfloat16* __restrict__ Al,
             const __nv_bfloat16* __restrict__ Bh, const __nv_bfloat16* __restrict__ Bl,
             const float* __restrict__ bias, float* __restrict__ C)
{
    extern __shared__ char smem[];
    const uint32_t sb = smem_u32(smem);
    const int tid = threadIdx.x, wid = tid >> 5, lane = tid & 31;
    const int bn = blockIdx.x * 128, bm = blockIdx.y * 128;
    const int wm = wid & 3, wn = wid >> 2;          // 4 x 2 warp grid

    const __nv_bfloat16* gAh = Ah + (size_t)bm * DM_;
    const __nv_bfloat16* gAl = Al + (size_t)bm * DM_;
    const __nv_bfloat16* gBh = Bh + (size_t)bn * DM_;
    const __nv_bfloat16* gBl = Bl + (size_t)bn * DM_;

    float acc[64];
    #pragma unroll
    for (int i = 0; i < 64; i++) acc[i] = 0.0f;

    // prologue: chunks 0, 1
    #pragma unroll
    for (int p = 0; p < 2; p++) {
        uint32_t b0 = sb + p * BUFB;
        load_chunk(b0 + OFF_AH, gAh + p * 64, tid);
        load_chunk(b0 + OFF_AL, gAl + p * 64, tid);
        load_chunk(b0 + OFF_BH, gBh + p * 64, tid);
        load_chunk(b0 + OFF_BL, gBl + p * 64, tid);
        CP_COMMIT();
    }

    // per-lane ldmatrix address components
    const int a_row = wm * 32 + (lane & 15);
    const int a_kb  = (lane >> 4) * 8;                         // k element offset
    const int b_n   = wn * 64 + ((lane >> 4) << 3) + (lane & 7);
    const int b_kb  = ((lane >> 3) & 1) * 8;

    for (int i = 0; i < 8; i++) {
        if (i < 7) asm volatile("cp.async.wait_group 1;" ::: "memory");
        else       asm volatile("cp.async.wait_group 0;" ::: "memory");
        __syncthreads();

        uint32_t bufb = sb + (uint32_t)(i & 1) * BUFB;
        uint32_t aBaseH = bufb + OFF_AH + (uint32_t)a_row * SROWB + a_kb * 2;
        uint32_t aBaseL = bufb + OFF_AL + (uint32_t)a_row * SROWB + a_kb * 2;
        uint32_t bBaseH = bufb + OFF_BH + (uint32_t)b_n * SROWB + b_kb * 2;
        uint32_t bBaseL = bufb + OFF_BL + (uint32_t)b_n * SROWB + b_kb * 2;

        #pragma unroll
        for (int ks = 0; ks < 4; ks++) {
            uint32_t a_h[2][4], a_l[2][4], b_h[4][4], b_l[4][4];
            #pragma unroll
            for (int ti = 0; ti < 2; ti++) {
                ldsm4(a_h[ti], aBaseH + ti * 16 * SROWB + ks * 32);
                ldsm4(a_l[ti], aBaseL + ti * 16 * SROWB + ks * 32);
            }
            #pragma unroll
            for (int tp = 0; tp < 4; tp++) {
                ldsm4(b_h[tp], bBaseH + tp * 16 * SROWB + ks * 32);
                ldsm4(b_l[tp], bBaseL + tp * 16 * SROWB + ks * 32);
            }
            #pragma unroll
            for (int ti = 0; ti < 2; ti++)
                #pragma unroll
                for (int tj = 0; tj < 8; tj++) {
                    float* c = acc + (ti * 8 + tj) * 4;
                    const uint32_t* bh = &b_h[tj >> 1][(tj & 1) * 2];
                    const uint32_t* bl = &b_l[tj >> 1][(tj & 1) * 2];
                    mma16816(c, a_h[ti], bh);
                    mma16816(c, a_h[ti], bl);
                    mma16816(c, a_l[ti], bh);
                }
        }
        __syncthreads();

        if (i + 2 < 8) {
            load_chunk(bufb + OFF_AH, gAh + (i + 2) * 64, tid);
            load_chunk(bufb + OFF_AL, gAl + (i + 2) * 64, tid);
            load_chunk(bufb + OFF_BH, gBh + (i + 2) * 64, tid);
            load_chunk(bufb + OFF_BL, gBl + (i + 2) * 64, tid);
            CP_COMMIT();
        }
    }

    // epilogue: c-frag (row = lane/4 [+8], col = 2*(lane%4))
    const int qrow = lane >> 2, qcol = (lane & 3) * 2;
    #pragma unroll
    for (int ti = 0; ti < 2; ti++)
        #pragma unroll
        for (int tj = 0; tj < 8; tj++) {
            const float* c = acc + (ti * 8 + tj) * 4;
            int row = bm + wm * 32 + ti * 16 + qrow;
            int col = bn + wn * 64 + tj * 8 + qcol;
            float b0 = bias[col], b1 = bias[col + 1];
            float2 v0 = make_float2(c[0] + b0, c[1] + b1);
            float2 v1 = make_float2(c[2] + b0, c[3] + b1);
            *(float2*)&C[(size_t)row * DM_ + col]       = v0;
            *(float2*)&C[(size_t)(row + 8) * DM_ + col] = v1;
        }
}

// ---------------------------------------------------------------------------
// vmean: coalesced partial sums + atomicAdd (g_vmean pre-zeroed)
// ---------------------------------------------------------------------------
__global__ void vmean_part()
{
    int b = blockIdx.x, jc = blockIdx.y;          // grid (4, 16)
    const float* base = g_v + ((size_t)b * S_ + jc * 128) * DM_;
    int tid = threadIdx.x;                        // 256
    float a0 = 0.f, a1 = 0.f;
    for (int j = 0; j < 128; j++) {
        a0 += base[(size_t)j * DM_ + tid];
        a1 += base[(size_t)j * DM_ + 256 + tid];
    }
    atomicAdd(&g_vmean[b * DM_ + tid],       a0 * (1.0f / S_));
    atomicAdd(&g_vmean[b * DM_ + 256 + tid], a1 * (1.0f / S_));
}

// ---------------------------------------------------------------------------
// Banded attention (unchanged from passing kernel)
// ---------------------------------------------------------------------------
__global__ __launch_bounds__(256)
void attn_kernel(const int* __restrict__ x_len)
{
    extern __shared__ float sm[];
    float* Qs      = sm;
    float* KVs     = Qs  + 32 * 68;
    float* Ss      = KVs + 32 * 68;
    float* rowinv  = Ss  + 32 * NKPAD;
    float* rowflag = rowinv + 32;

    const int qt = blockIdx.x, h = blockIdx.y, b = blockIdx.z;
    const int i0 = qt * QT;
    const int kbeg = max(0, i0 - 128);
    const int kend = min(S_, i0 + QT + 128);
    const int nk = kend - kbeg;
    const int nch = (nk + 31) >> 5;
    const int xlen = x_len[b];
    const int tid = threadIdx.x;

    const int qi   = tid >> 3;
    const int dblk = (tid & 7) * 8;

    {
        const float* src = g_q + ((size_t)(b * S_ + i0 + qi)) * DM_ + h * D_ + dblk;
        *(float4*)&Qs[qi * 68 + dblk]     = *(const float4*)src;
        *(float4*)&Qs[qi * 68 + dblk + 4] = *(const float4*)(src + 4);
    }

    const int ty = tid >> 4, tx = tid & 15;

    for (int c = 0; c < nch; c++) {
        int jb = kbeg + c * 32;
        __syncthreads();
        {
            int j = jb + qi;
            float4 x0 = make_float4(0.f, 0.f, 0.f, 0.f), x1 = x0;
            if (j < kend) {
                const float* src = g_k + ((size_t)(b * S_ + j)) * DM_ + h * D_ + dblk;
                x0 = *(const float4*)src;
                x1 = *(const float4*)(src + 4);
            }
            *(float4*)&KVs[qi * 68 + dblk]     = x0;
            *(float4*)&KVs[qi * 68 + dblk + 4] = x1;
        }
        __syncthreads();

        float s00 = 0.f, s01 = 0.f, s10 = 0.f, s11 = 0.f;
        #pragma unroll
        for (int cc = 0; cc < 16; cc++) {
            float4 qa = *(const float4*)&Qs[(2 * ty + 0) * 68 + cc * 4];
            float4 qb = *(const float4*)&Qs[(2 * ty + 1) * 68 + cc * 4];
            float4 ka = *(const float4*)&KVs[(2 * tx + 0) * 68 + cc * 4];
            float4 kb = *(const float4*)&KVs[(2 * tx + 1) * 68 + cc * 4];
            s00 += qa.x * ka.x + qa.y * ka.y + qa.z * ka.z + qa.w * ka.w;
            s01 += qa.x * kb.x + qa.y * kb.y + qa.z * kb.z + qa.w * kb.w;
            s10 += qb.x * ka.x + qb.y * ka.y + qb.z * ka.z + qb.w * ka.w;
            s11 += qb.x * kb.x + qb.y * kb.y + qb.z * kb.z + qb.w * kb.w;
        }
        float sv[2][2] = {{s00, s01}, {s10, s11}};
        #pragma unroll
        for (int qq = 0; qq < 2; qq++) {
            #pragma unroll
            for (int kk = 0; kk < 2; kk++) {
                int i = i0 + 2 * ty + qq;
                int j = jb + 2 * tx + kk;
                bool valid = (j - i <= 128) && (i - j <= 128) && (j < xlen) && (j < kend);
                Ss[(2 * ty + qq) * NKPAD + c * 32 + 2 * tx + kk] =
                    valid ? sv[qq][kk] * 0.125f : -1e30f;
            }
        }
    }
    __syncthreads();

    const int wid = tid >> 5, lane = tid & 31;
    const int nkr = nch * 32;
    for (int rr = 0; rr < 4; rr++) {
        int r = wid + rr * 8;
        float m = -3e38f;
        for (int c = lane; c < nkr; c += 32) m = fmaxf(m, Ss[r * NKPAD + c]);
        #pragma unroll
        for (int o = 16; o; o >>= 1) m = fmaxf(m, __shfl_xor_sync(0xffffffffu, m, o));
        float sum = 0.f;
        for (int c = lane; c < nkr; c += 32) {
            float p = __expf(Ss[r * NKPAD + c] - m);
            Ss[r * NKPAD + c] = p;
            sum += p;
        }
        #pragma unroll
        for (int o = 16; o; o >>= 1) sum += __shfl_xor_sync(0xffffffffu, sum, o);
        if (lane == 0) {
            rowinv[r]  = 1.0f / sum;
            rowflag[r] = (m <= -1e29f) ? 1.0f : 0.0f;
        }
    }

    float acc[8] = {0.f, 0.f, 0.f, 0.f, 0.f, 0.f, 0.f, 0.f};
    for (int c = 0; c < nch; c++) {
        int jb = kbeg + c * 32;
        __syncthreads();
        {
            int j = jb + qi;
            float4 x0 = make_float4(0.f, 0.f, 0.f, 0.f), x1 = x0;
            if (j < kend) {
                const float* src = g_v + ((size_t)(b * S_ + j)) * DM_ + h * D_ + dblk;
                x0 = *(const float4*)src;
                x1 = *(const float4*)(src + 4);
            }
            *(float4*)&KVs[qi * 68 + dblk]     = x0;
            *(float4*)&KVs[qi * 68 + dblk + 4] = x1;
        }
        __syncthreads();
        #pragma unroll
        for (int j4 = 0; j4 < 8; j4++) {
            float4 p4 = *(const float4*)&Ss[qi * NKPAD + c * 32 + j4 * 4];
            float pv[4] = {p4.x, p4.y, p4.z, p4.w};
            #pragma unroll
            for (int t = 0; t < 4; t++) {
                int j = j4 * 4 + t;
                float4 v0 = *(const float4*)&KVs[j * 68 + dblk];
                float4 v1 = *(const float4*)&KVs[j * 68 + dblk + 4];
                acc[0] += pv[t] * v0.x; acc[1] += pv[t] * v0.y;
                acc[2] += pv[t] * v0.z; acc[3] += pv[t] * v0.w;
                acc[4] += pv[t] * v1.x; acc[5] += pv[t] * v1.y;
                acc[6] += pv[t] * v1.z; acc[7] += pv[t] * v1.w;
            }
        }
    }

    float inv  = rowinv[qi];
    bool  flag = rowflag[qi] > 0.5f;
    float* dst = g_ctx + ((size_t)(b * S_ + i0 + qi)) * DM_ + h * D_ + dblk;
    const float* vm = g_vmean + b * DM_ + h * D_ + dblk;
    float4 o0, o1;
    o0.x = flag ? vm[0] : acc[0] * inv;
    o0.y = flag ? vm[1] : acc[1] * inv;
    o0.z = flag ? vm[2] : acc[2] * inv;
    o0.w = flag ? vm[3] : acc[3] * inv;
    o1.x = flag ? vm[4] : acc[4] * inv;
    o1.y = flag ? vm[5] : acc[5] * inv;
    o1.z = flag ? vm[6] : acc[6] * inv;
    o1.w = flag ? vm[7] : acc[7] * inv;
    *(float4*)dst       = o0;
    *(float4*)(dst + 4) = o1;
}

// ---------------------------------------------------------------------------
extern "C" void kernel_launch(void* const* d_in, const int* in_sizes, int n_in,
                              void* d_out, int out_size)
{
    (void)in_sizes; (void)n_in; (void)out_size;
    const float* x  = (const float*)d_in[0];
    const float* Wq = (const float*)d_in[1];
    const float* bq = (const float*)d_in[2];
    const float* Wk = (const float*)d_in[3];
    const float* bk = (const float*)d_in[4];
    const float* Wv = (const float*)d_in[5];
    const float* bv = (const float*)d_in[6];
    const float* Wo = (const float*)d_in[7];
    const float* bo = (const float*)d_in[8];
    const int*   xl = (const int*)d_in[9];
    float* out = (float*)d_out;

    float *gq, *gk, *gv, *gctx, *gvm;
    __nv_bfloat16 *gah, *gal, *gwth, *gwtl;
    cudaGetSymbolAddress((void**)&gq,   g_q);
    cudaGetSymbolAddress((void**)&gk,   g_k);
    cudaGetSymbolAddress((void**)&gv,   g_v);
    cudaGetSymbolAddress((void**)&gctx, g_ctx);
    cudaGetSymbolAddress((void**)&gvm,  g_vmean);
    cudaGetSymbolAddress((void**)&gah,  g_ah);
    cudaGetSymbolAddress((void**)&gal,  g_al);
    cudaGetSymbolAddress((void**)&gwth, g_wth);
    cudaGetSymbolAddress((void**)&gwtl, g_wtl);

    // weight transpose + split (4 weights)
    dim3 wtg(16, 16), wtb(32, 8);
    prep_wt<<<wtg, wtb>>>(Wq, gwth + 0 * DM_ * DM_, gwtl + 0 * DM_ * DM_);
    prep_wt<<<wtg, wtb>>>(Wk, gwth + 1 * DM_ * DM_, gwtl + 1 * DM_ * DM_);
    prep_wt<<<wtg, wtb>>>(Wv, gwth + 2 * DM_ * DM_, gwtl + 2 * DM_ * DM_);
    prep_wt<<<wtg, wtb>>>(Wo, gwth + 3 * DM_ * DM_, gwtl + 3 * DM_ * DM_);

    // x -> bf16 hi/lo
    prep_split<<<2048, 256>>>(x, gah, gal, MROWS * DM_);

    cudaFuncSetAttribute(gemm_tc, cudaFuncAttributeMaxDynamicSharedMemorySize, GSMEM_TOT);
    dim3 gg(DM_ / 128, MROWS / 128);   // (4, 64) = 256 CTAs
    gemm_tc<<<gg, 256, GSMEM_TOT>>>(gah, gal, gwth + 0 * DM_ * DM_, gwtl + 0 * DM_ * DM_, bq, gq);
    gemm_tc<<<gg, 256, GSMEM_TOT>>>(gah, gal, gwth + 1 * DM_ * DM_, gwtl + 1 * DM_ * DM_, bk, gk);
    gemm_tc<<<gg, 256, GSMEM_TOT>>>(gah, gal, gwth + 2 * DM_ * DM_, gwtl + 2 * DM_ * DM_, bv, gv);

    cudaMemsetAsync(gvm, 0, B_ * DM_ * sizeof(float));
    vmean_part<<<dim3(B_, 16), 256>>>();

    const int smem_bytes = (32 * 68 * 2 + 32 * NKPAD + 64) * sizeof(float);
    cudaFuncSetAttribute(attn_kernel, cudaFuncAttributeMaxDynamicSharedMemorySize, smem_bytes);
    attn_kernel<<<dim3(S_ / QT, H_, B_), 256, smem_bytes>>>(xl);

    // ctx -> bf16 hi/lo (reuse A buffers), output projection
    prep_split<<<2048, 256>>>(gctx, gah, gal, MROWS * DM_);
    gemm_tc<<<gg, 256, GSMEM_TOT>>>(gah, gal, gwth + 3 * DM_ * DM_, gwtl + 3 * DM_ * DM_, bo, out);
}

// round 12
// speedup vs baseline: 2.7954x; 2.0016x over previous
#include <cuda_runtime.h>
#include <cuda_bf16.h>
#include <cstdint>

#define B_  4
#define S_  2048
#define DM_ 512
#define H_  8
#define MROWS (B_*S_)     // 8192

// ---------------- scratch (__device__ globals, allocation-free) ----------------
__device__ __nv_bfloat16 g_ah[MROWS*DM_];   // A hi (x, later ctx)
__device__ __nv_bfloat16 g_al[MROWS*DM_];   // A lo
__device__ __nv_bfloat16 g_qh[MROWS*DM_];
__device__ __nv_bfloat16 g_ql[MROWS*DM_];
__device__ __nv_bfloat16 g_kh[MROWS*DM_];
__device__ __nv_bfloat16 g_kl[MROWS*DM_];
__device__ __nv_bfloat16 g_vh[MROWS*DM_];
__device__ __nv_bfloat16 g_vl[MROWS*DM_];
__device__ __nv_bfloat16 g_wth[4*DM_*DM_];  // W^T hi (q,k,v,o)
__device__ __nv_bfloat16 g_wtl[4*DM_*DM_];
__device__ float g_vmean[B_*DM_];

// ---------------- helpers ----------------
__device__ __forceinline__ uint32_t smem_u32(const void* p) {
    uint32_t a;
    asm("{ .reg .u64 t; cvta.to.shared.u64 t, %1; cvt.u32.u64 %0, t; }" : "=r"(a) : "l"(p));
    return a;
}
__device__ __forceinline__ void cp16(uint32_t dst, const void* src) {
    asm volatile("cp.async.cg.shared.global [%0], [%1], 16;" :: "r"(dst), "l"(src) : "memory");
}
#define CP_COMMIT() asm volatile("cp.async.commit_group;" ::: "memory")

__device__ __forceinline__ void ldsm4(uint32_t* r, uint32_t addr) {
    asm volatile("ldmatrix.sync.aligned.m8n8.x4.shared.b16 {%0,%1,%2,%3}, [%4];"
                 : "=r"(r[0]), "=r"(r[1]), "=r"(r[2]), "=r"(r[3]) : "r"(addr));
}
__device__ __forceinline__ void ldsm4t(uint32_t* r, uint32_t addr) {
    asm volatile("ldmatrix.sync.aligned.m8n8.x4.trans.shared.b16 {%0,%1,%2,%3}, [%4];"
                 : "=r"(r[0]), "=r"(r[1]), "=r"(r[2]), "=r"(r[3]) : "r"(addr));
}
__device__ __forceinline__ void mma16816(float* c, const uint32_t* a, const uint32_t* b) {
    asm volatile(
        "mma.sync.aligned.m16n8k16.row.col.f32.bf16.bf16.f32 "
        "{%0,%1,%2,%3}, {%4,%5,%6,%7}, {%8,%9}, {%0,%1,%2,%3};"
        : "+f"(c[0]), "+f"(c[1]), "+f"(c[2]), "+f"(c[3])
        : "r"(a[0]), "r"(a[1]), "r"(a[2]), "r"(a[3]), "r"(b[0]), "r"(b[1]));
}
__device__ __forceinline__ void split2(float v0, float v1, uint32_t& hp, uint32_t& lp) {
    __nv_bfloat16 h0 = __float2bfloat16(v0);
    __nv_bfloat16 h1 = __float2bfloat16(v1);
    __nv_bfloat16 g0 = __float2bfloat16(v0 - __bfloat162float(h0));
    __nv_bfloat16 g1 = __float2bfloat16(v1 - __bfloat162float(h1));
    hp = (uint32_t)__bfloat16_as_ushort(h0) | ((uint32_t)__bfloat16_as_ushort(h1) << 16);
    lp = (uint32_t)__bfloat16_as_ushort(g0) | ((uint32_t)__bfloat16_as_ushort(g1) << 16);
}
__device__ __forceinline__ float bf_lo(uint32_t u) {
    return __bfloat162float(__ushort_as_bfloat16((unsigned short)(u & 0xffff)));
}
__device__ __forceinline__ float bf_hi(uint32_t u) {
    return __bfloat162float(__ushort_as_bfloat16((unsigned short)(u >> 16)));
}

// ---------------------------------------------------------------------------
// prep: split fp32 -> bf16 hi/lo
// ---------------------------------------------------------------------------
__global__ void prep_split(const float* __restrict__ src,
                           __nv_bfloat16* __restrict__ hi,
                           __nv_bfloat16* __restrict__ lo, int n)
{
    int i = blockIdx.x * blockDim.x + threadIdx.x;
    for (; i < n; i += gridDim.x * blockDim.x) {
        float v = src[i];
        __nv_bfloat16 h = __float2bfloat16(v);
        hi[i] = h;
        lo[i] = __float2bfloat16(v - __bfloat162float(h));
    }
}

// transpose + split all 4 weights: W[512,512] -> Wt[n][k] hi/lo, z selects W
__global__ void prep_wt4(const float* __restrict__ W0, const float* __restrict__ W1,
                         const float* __restrict__ W2, const float* __restrict__ W3)
{
    const float* W = (blockIdx.z == 0) ? W0 : (blockIdx.z == 1) ? W1
                   : (blockIdx.z == 2) ? W2 : W3;
    __nv_bfloat16* th = g_wth + (size_t)blockIdx.z * DM_ * DM_;
    __nv_bfloat16* tl = g_wtl + (size_t)blockIdx.z * DM_ * DM_;
    __shared__ float t[32][33];
    int bk = blockIdx.x * 32, bn = blockIdx.y * 32;
    int tx = threadIdx.x, ty = threadIdx.y;   // 32 x 8
    #pragma unroll
    for (int i = 0; i < 32; i += 8)
        t[ty + i][tx] = W[(size_t)(bk + ty + i) * DM_ + bn + tx];
    __syncthreads();
    #pragma unroll
    for (int i = 0; i < 32; i += 8) {
        float v = t[tx][ty + i];
        __nv_bfloat16 h = __float2bfloat16(v);
        size_t o = (size_t)(bn + ty + i) * DM_ + bk + tx;
        th[o] = h;
        tl[o] = __float2bfloat16(v - __bfloat162float(h));
    }
}

// ---------------------------------------------------------------------------
// HMMA split-bf16 GEMM: C = A*W + bias.  CTA 128x128, 8 warps (4x2),
// K chunk 32, cp.async 2-buf, 80B smem rows (conflict-free ldmatrix).
// Output: fp32 (Cf) or bf16 hi/lo (Ch/Cl).
// ---------------------------------------------------------------------------
#define SROWB 80
#define TILEB (128 * SROWB)        // 10240
#define OFF_AH 0
#define OFF_AL (TILEB)
#define OFF_BH (2 * TILEB)
#define OFF_BL (3 * TILEB)
#define BUFB   (4 * TILEB)         // 40960
#define GSMEM_TOT (2 * BUFB)       // 81920

__device__ __forceinline__ void load_chunk32(uint32_t dst, const __nv_bfloat16* g, int tid)
{
    // 128 rows x 64B; global row stride 1024B
    #pragma unroll
    for (int it = 0; it < 2; it++) {
        int idx = tid + it * 256;
        int r = idx >> 2, c = idx & 3;
        cp16(dst + r * SROWB + c * 16, (const char*)g + (size_t)r * 1024 + c * 16);
    }
}

__global__ __launch_bounds__(256, 2)
void gemm_tc(const __nv_bfloat16* __restrict__ Ah, const __nv_bfloat16* __restrict__ Al,
             const __nv_bfloat16* __restrict__ Bh, const __nv_bfloat16* __restrict__ Bl,
             const float* __restrict__ bias, float* __restrict__ Cf,
             __nv_bfloat16* __restrict__ Ch, __nv_bfloat16* __restrict__ Cl)
{
    extern __shared__ char smem[];
    const uint32_t sb = smem_u32(smem);
    const int tid = threadIdx.x, wid = tid >> 5, lane = tid & 31;
    const int bn = blockIdx.x * 128, bm = blockIdx.y * 128;
    const int wm = wid & 3, wn = wid >> 2;          // 4 x 2 warp grid

    const __nv_bfloat16* gAh = Ah + (size_t)bm * DM_;
    const __nv_bfloat16* gAl = Al + (size_t)bm * DM_;
    const __nv_bfloat16* gBh = Bh + (size_t)bn * DM_;
    const __nv_bfloat16* gBl = Bl + (size_t)bn * DM_;

    float acc[64];
    #pragma unroll
    for (int i = 0; i < 64; i++) acc[i] = 0.0f;

    #pragma unroll
    for (int p = 0; p < 2; p++) {
        uint32_t b0 = sb + p * BUFB;
        load_chunk32(b0 + OFF_AH, gAh + p * 32, tid);
        load_chunk32(b0 + OFF_AL, gAl + p * 32, tid);
        load_chunk32(b0 + OFF_BH, gBh + p * 32, tid);
        load_chunk32(b0 + OFF_BL, gBl + p * 32, tid);
        CP_COMMIT();
    }

    for (int i = 0; i < 16; i++) {
        if (i < 15) asm volatile("cp.async.wait_group 1;" ::: "memory");
        else        asm volatile("cp.async.wait_group 0;" ::: "memory");
        __syncthreads();

        uint32_t bufb = sb + (uint32_t)(i & 1) * BUFB;
        #pragma unroll
        for (int ks = 0; ks < 2; ks++) {
            uint32_t a_h[2][4], a_l[2][4];
            #pragma unroll
            for (int ti = 0; ti < 2; ti++) {
                uint32_t ar = (uint32_t)(wm * 32 + ti * 16 + (lane & 15)) * SROWB
                            + (uint32_t)(ks * 16 + (lane >> 4) * 8) * 2;
                ldsm4(a_h[ti], bufb + OFF_AH + ar);
                ldsm4(a_l[ti], bufb + OFF_AL + ar);
            }
            #pragma unroll
            for (int tp = 0; tp < 4; tp++) {
                uint32_t b_h[4], b_l[4];
                uint32_t br = (uint32_t)(wn * 64 + tp * 16 + ((lane >> 4) << 3) + (lane & 7)) * SROWB
                            + (uint32_t)(ks * 16 + ((lane >> 3) & 1) * 8) * 2;
                ldsm4(b_h, bufb + OFF_BH + br);
                ldsm4(b_l, bufb + OFF_BL + br);
                #pragma unroll
                for (int ti = 0; ti < 2; ti++)
                    #pragma unroll
                    for (int half = 0; half < 2; half++) {
                        float* c = acc + (ti * 8 + tp * 2 + half) * 4;
                        mma16816(c, a_h[ti], &b_h[half * 2]);
                        mma16816(c, a_h[ti], &b_l[half * 2]);
                        mma16816(c, a_l[ti], &b_h[half * 2]);
                    }
            }
        }
        __syncthreads();

        if (i + 2 < 16) {
            load_chunk32(bufb + OFF_AH, gAh + (i + 2) * 32, tid);
            load_chunk32(bufb + OFF_AL, gAl + (i + 2) * 32, tid);
            load_chunk32(bufb + OFF_BH, gBh + (i + 2) * 32, tid);
            load_chunk32(bufb + OFF_BL, gBl + (i + 2) * 32, tid);
            CP_COMMIT();
        }
    }

    // epilogue
    const int qrow = lane >> 2, qcol = (lane & 3) * 2;
    #pragma unroll
    for (int ti = 0; ti < 2; ti++)
        #pragma unroll
        for (int tj = 0; tj < 8; tj++) {
            const float* c = acc + (ti * 8 + tj) * 4;
            int row = bm + wm * 32 + ti * 16 + qrow;
            int col = bn + wn * 64 + tj * 8 + qcol;
            float b0 = bias[col], b1 = bias[col + 1];
            float v0 = c[0] + b0, v1 = c[1] + b1;
            float v2 = c[2] + b0, v3 = c[3] + b1;
            if (Cf) {
                *(float2*)&Cf[(size_t)row * DM_ + col]       = make_float2(v0, v1);
                *(float2*)&Cf[(size_t)(row + 8) * DM_ + col] = make_float2(v2, v3);
            } else {
                uint32_t hp, lp;
                split2(v0, v1, hp, lp);
                *(uint32_t*)&Ch[(size_t)row * DM_ + col] = hp;
                *(uint32_t*)&Cl[(size_t)row * DM_ + col] = lp;
                split2(v2, v3, hp, lp);
                *(uint32_t*)&Ch[(size_t)(row + 8) * DM_ + col] = hp;
                *(uint32_t*)&Cl[(size_t)(row + 8) * DM_ + col] = lp;
            }
        }
}

// ---------------------------------------------------------------------------
// vmean[b,c] = mean_j v[b,j,c]  (from hi+lo; g_vmean pre-zeroed)
// ---------------------------------------------------------------------------
__global__ void vmean_part()
{
    int b = blockIdx.x, jc = blockIdx.y;          // grid (4, 16)
    const __nv_bfloat16* bh = g_vh + ((size_t)b * S_ + jc * 128) * DM_;
    const __nv_bfloat16* bl = g_vl + ((size_t)b * S_ + jc * 128) * DM_;
    int tid = threadIdx.x;                        // 256
    float a0 = 0.f, a1 = 0.f;
    for (int j = 0; j < 128; j++) {
        size_t o = (size_t)j * DM_;
        a0 += __bfloat162float(bh[o + tid])       + __bfloat162float(bl[o + tid]);
        a1 += __bfloat162float(bh[o + 256 + tid]) + __bfloat162float(bl[o + 256 + tid]);
    }
    atomicAdd(&g_vmean[b * DM_ + tid],       a0 * (1.0f / S_));
    atomicAdd(&g_vmean[b * DM_ + 256 + tid], a1 * (1.0f / S_));
}

// ---------------------------------------------------------------------------
// HMMA banded attention. Block = (64-query tile, head, batch), 256 threads.
// ---------------------------------------------------------------------------
#define QTA 64
#define PST 1424u                  // bytes per S/P row (89*16; 356 banks == 4 mod 32)
#define PLO 704u                   // lo plane offset within row
#define AOQH 0
#define AOQL 9216
#define AOKB 18432                 // K/V double buffers (hi 9216 + lo 9216 each)
#define KBUF 18432
#define AOS  (AOKB + 2 * KBUF)     // 55296
#define AOSTAT (AOS + 64 * 1424)   // 146432
#define ASMEM (AOSTAT + 512)       // 146944

__device__ __forceinline__ void attn_ldkv(uint32_t dstbase, const __nv_bfloat16* gh,
                                          const __nv_bfloat16* gl, int jb, int tid)
{
    #pragma unroll
    for (int it = 0; it < 4; it++) {
        int idx = tid + it * 256;
        int plane = idx >> 9, r = (idx >> 3) & 63, cc = idx & 7;
        int j = jb + r; if (j > S_ - 1) j = S_ - 1;
        const __nv_bfloat16* src = (plane ? gl : gh) + (size_t)j * DM_ + cc * 8;
        cp16(dstbase + plane * 9216 + r * 144 + cc * 16, src);
    }
}

__global__ __launch_bounds__(256, 1)
void attn_hmma(const int* __restrict__ x_len)
{
    extern __shared__ char smem[];
    const uint32_t sb = smem_u32(smem);
    const int tid = threadIdx.x, wid = tid >> 5, lane = tid & 31;
    const int qt = blockIdx.x, h = blockIdx.y, b = blockIdx.z;
    const int i0 = qt * QTA;
    const int kbeg = max(0, i0 - 128);
    const int kend = min(S_, i0 + QTA + 128);
    const int nkc = (kend - kbeg + 63) >> 6;       // 3..5
    const int T = 2 * nkc;
    const int xlen = x_len[b];

    const size_t hb = (size_t)(b * S_) * DM_ + h * 64;
    const __nv_bfloat16* qh = g_qh + hb; const __nv_bfloat16* ql = g_ql + hb;
    const __nv_bfloat16* kh = g_kh + hb; const __nv_bfloat16* kl = g_kl + hb;
    const __nv_bfloat16* vh = g_vh + hb; const __nv_bfloat16* vl = g_vl + hb;

    float* rowinv  = (float*)(smem + AOSTAT);
    float* rowflag = rowinv + 64;

    // Q tile load (rides with stage-0 group)
    #pragma unroll
    for (int it = 0; it < 4; it++) {
        int idx = tid + it * 256;
        int plane = idx >> 9, r = (idx >> 3) & 63, cc = idx & 7;
        const __nv_bfloat16* src = (plane ? ql : qh) + (size_t)(i0 + r) * DM_ + cc * 8;
        cp16(sb + (plane ? AOQL : AOQH) + r * 144 + cc * 16, src);
    }
    attn_ldkv(sb + AOKB, kh, kl, kbeg, tid);
    CP_COMMIT();
    attn_ldkv(sb + AOKB + KBUF, kh, kl, kbeg + 64, tid);
    CP_COMMIT();

    float pacc[2][2][4];
    #pragma unroll
    for (int a = 0; a < 2; a++)
        #pragma unroll
        for (int bb = 0; bb < 2; bb++)
            #pragma unroll
            for (int cix = 0; cix < 4; cix++) pacc[a][bb][cix] = 0.0f;

    const int wm = wid & 1, wn = wid >> 1;   // 2 x 4 warps

    for (int t = 0; t < T; t++) {
        if (t < T - 1) asm volatile("cp.async.wait_group 1;" ::: "memory");
        else           asm volatile("cp.async.wait_group 0;" ::: "memory");
        __syncthreads();
        const uint32_t kbuf = sb + AOKB + (uint32_t)(t & 1) * KBUF;

        if (t < nkc) {
            // ---- scores chunk t: [64 q] x [64 keys], warp = 32q x 16k ----
            float sacc[2][2][4];
            #pragma unroll
            for (int a = 0; a < 2; a++)
                #pragma unroll
                for (int bb = 0; bb < 2; bb++)
                    #pragma unroll
                    for (int cix = 0; cix < 4; cix++) sacc[a][bb][cix] = 0.0f;

            #pragma unroll
            for (int ks = 0; ks < 4; ks++) {
                uint32_t a_h[2][4], a_l[2][4], b_h[4], b_l[4];
                #pragma unroll
                for (int mt = 0; mt < 2; mt++) {
                    uint32_t ar = (uint32_t)(wm * 32 + mt * 16 + (lane & 15)) * 144
                                + (uint32_t)(ks * 16 + (lane >> 4) * 8) * 2;
                    ldsm4(a_h[mt], sb + AOQH + ar);
                    ldsm4(a_l[mt], sb + AOQL + ar);
                }
                uint32_t br = (uint32_t)(wn * 16 + ((lane >> 4) << 3) + (lane & 7)) * 144
                            + (uint32_t)(ks * 16 + ((lane >> 3) & 1) * 8) * 2;
                ldsm4(b_h, kbuf + br);
                ldsm4(b_l, kbuf + 9216 + br);
                #pragma unroll
                for (int mt = 0; mt < 2; mt++)
                    #pragma unroll
                    for (int nt = 0; nt < 2; nt++) {
                        float* c = sacc[mt][nt];
                        mma16816(c, a_h[mt], &b_h[nt * 2]);
                        mma16816(c, a_h[mt], &b_l[nt * 2]);
                        mma16816(c, a_l[mt], &b_h[nt * 2]);
                    }
            }
            // write S as bf16 hi/lo with mask + 1/sqrt(64) scale
            const int cg0 = t * 64;
            #pragma unroll
            for (int mt = 0; mt < 2; mt++)
                #pragma unroll
                for (int nt = 0; nt < 2; nt++) {
                    int cl = wn * 16 + nt * 8 + (lane & 3) * 2;
                    int j0 = kbeg + cg0 + cl, j1 = j0 + 1;
                    #pragma unroll
                    for (int hr = 0; hr < 2; hr++) {
                        int r = wm * 32 + mt * 16 + (lane >> 2) + hr * 8;
                        int i = i0 + r;
                        float v0 = sacc[mt][nt][hr * 2 + 0] * 0.125f;
                        float v1 = sacc[mt][nt][hr * 2 + 1] * 0.125f;
                        bool ok0 = (j0 - i <= 128) && (i - j0 <= 128) && (j0 < xlen) && (j0 < kend);
                        bool ok1 = (j1 - i <= 128) && (i - j1 <= 128) && (j1 < xlen) && (j1 < kend);
                        if (!ok0) v0 = -1e30f;
                        if (!ok1) v1 = -1e30f;
                        uint32_t hp, lp;
                        split2(v0, v1, hp, lp);
                        char* base = smem + AOS + (size_t)r * PST + (size_t)(cg0 + cl) * 2;
                        *(uint32_t*)base         = hp;
                        *(uint32_t*)(base + PLO) = lp;
                    }
                }
        } else {
            // ---- PV chunk t-nkc: O[64 q x 64 d], warp = 32q x 16d ----
            const int cc_ = t - nkc;
            #pragma unroll
            for (int ks = 0; ks < 4; ks++) {
                uint32_t p_h[2][4], p_l[2][4], v_h[4], v_l[4];
                #pragma unroll
                for (int mt = 0; mt < 2; mt++) {
                    uint32_t ar = sb + AOS + (uint32_t)(wm * 32 + mt * 16 + (lane & 15)) * PST
                                + (uint32_t)(cc_ * 64 + ks * 16 + (lane >> 4) * 8) * 2;
                    ldsm4(p_h[mt], ar);
                    ldsm4(p_l[mt], ar + PLO);
                }
                uint32_t vr = (uint32_t)(ks * 16 + (lane & 15)) * 144
                            + (uint32_t)(wn * 16 + (lane >> 4) * 8) * 2;
                ldsm4t(v_h, kbuf + vr);
                ldsm4t(v_l, kbuf + 9216 + vr);
                #pragma unroll
                for (int mt = 0; mt < 2; mt++)
                    #pragma unroll
                    for (int nt = 0; nt < 2; nt++) {
                        float* c = pacc[mt][nt];
                        mma16816(c, p_h[mt], &v_h[nt * 2]);
                        mma16816(c, p_h[mt], &v_l[nt * 2]);
                        mma16816(c, p_l[mt], &v_h[nt * 2]);
                    }
            }
        }
        __syncthreads();

        if (t + 2 < T) {
            int s = t + 2;
            const __nv_bfloat16* gh = (s < nkc) ? kh : vh;
            const __nv_bfloat16* gl = (s < nkc) ? kl : vl;
            int jb = kbeg + ((s < nkc) ? s : s - nkc) * 64;
            attn_ldkv(sb + AOKB + (uint32_t)(s & 1) * KBUF, gh, gl, jb, tid);
            CP_COMMIT();
        }

        if (t == nkc - 1) {
            // ---- softmax: warp handles rows wid*8 .. wid*8+7; in-place S->P ----
            const int npair = nkc * 32;
            #pragma unroll
            for (int rr = 0; rr < 8; rr++) {
                int r = wid * 8 + rr;
                char* rbase = smem + AOS + (size_t)r * PST;
                float m = -3.0e38f;
                for (int p = lane; p < npair; p += 32) {
                    uint32_t hp = *(uint32_t*)(rbase + p * 4);
                    uint32_t lp = *(uint32_t*)(rbase + PLO + p * 4);
                    float s0 = bf_lo(hp) + bf_lo(lp);
                    float s1 = bf_hi(hp) + bf_hi(lp);
                    m = fmaxf(m, fmaxf(s0, s1));
                }
                #pragma unroll
                for (int o = 16; o; o >>= 1) m = fmaxf(m, __shfl_xor_sync(0xffffffffu, m, o));
                float sum = 0.f;
                for (int p = lane; p < npair; p += 32) {
                    uint32_t hp = *(uint32_t*)(rbase + p * 4);
                    uint32_t lp = *(uint32_t*)(rbase + PLO + p * 4);
                    float s0 = bf_lo(hp) + bf_lo(lp);
                    float s1 = bf_hi(hp) + bf_hi(lp);
                    float p0 = __expf(fminf(s0 - m, 0.0f));
                    float p1 = __expf(fminf(s1 - m, 0.0f));
                    sum += p0 + p1;
                    uint32_t nh, nl;
                    split2(p0, p1, nh, nl);
                    *(uint32_t*)(rbase + p * 4)       = nh;
                    *(uint32_t*)(rbase + PLO + p * 4) = nl;
                }
                #pragma unroll
                for (int o = 16; o; o >>= 1) sum += __shfl_xor_sync(0xffffffffu, sum, o);
                if (lane == 0) {
                    rowinv[r]  = 1.0f / sum;
                    rowflag[r] = (m <= -1e29f) ? 1.0f : 0.0f;
                }
            }
        }
    }

    // epilogue: ctx -> g_ah/g_al (bf16 hi/lo) for the output projection
    const float* vmrow = g_vmean + b * DM_ + h * 64;
    __nv_bfloat16* cth = g_ah + hb;
    __nv_bfloat16* ctl = g_al + hb;
    #pragma unroll
    for (int mt = 0; mt < 2; mt++)
        #pragma unroll
        for (int nt = 0; nt < 2; nt++)
            #pragma unroll
            for (int hr = 0; hr < 2; hr++) {
                int r = wm * 32 + mt * 16 + (lane >> 2) + hr * 8;
                int d = wn * 16 + nt * 8 + (lane & 3) * 2;
                float inv = rowinv[r];
                bool  fl  = rowflag[r] > 0.5f;
                float o0 = fl ? vmrow[d]     : pacc[mt][nt][hr * 2 + 0] * inv;
                float o1 = fl ? vmrow[d + 1] : pacc[mt][nt][hr * 2 + 1] * inv;
                uint32_t hp, lp;
                split2(o0, o1, hp, lp);
                size_t off = (size_t)(i0 + r) * DM_ + d;
                *(uint32_t*)&cth[off] = hp;
                *(uint32_t*)&ctl[off] = lp;
            }
}

// ---------------------------------------------------------------------------
extern "C" void kernel_launch(void* const* d_in, const int* in_sizes, int n_in,
                              void* d_out, int out_size)
{
    (void)in_sizes; (void)n_in; (void)out_size;
    const float* x  = (const float*)d_in[0];
    const float* Wq = (const float*)d_in[1];
    const float* bq = (const float*)d_in[2];
    const float* Wk = (const float*)d_in[3];
    const float* bk = (const float*)d_in[4];
    const float* Wv = (const float*)d_in[5];
    const float* bv = (const float*)d_in[6];
    const float* Wo = (const float*)d_in[7];
    const float* bo = (const float*)d_in[8];
    const int*   xl = (const int*)d_in[9];
    float* out = (float*)d_out;

    float* gvm;
    __nv_bfloat16 *gah, *gal, *gqh, *gql, *gkh, *gkl, *gvh, *gvl, *gwth, *gwtl;
    cudaGetSymbolAddress((void**)&gvm,  g_vmean);
    cudaGetSymbolAddress((void**)&gah,  g_ah);
    cudaGetSymbolAddress((void**)&gal,  g_al);
    cudaGetSymbolAddress((void**)&gqh,  g_qh);
    cudaGetSymbolAddress((void**)&gql,  g_ql);
    cudaGetSymbolAddress((void**)&gkh,  g_kh);
    cudaGetSymbolAddress((void**)&gkl,  g_kl);
    cudaGetSymbolAddress((void**)&gvh,  g_vh);
    cudaGetSymbolAddress((void**)&gvl,  g_vl);
    cudaGetSymbolAddress((void**)&gwth, g_wth);
    cudaGetSymbolAddress((void**)&gwtl, g_wtl);

    prep_wt4<<<dim3(16, 16, 4), dim3(32, 8)>>>(Wq, Wk, Wv, Wo);
    prep_split<<<2048, 256>>>(x, gah, gal, MROWS * DM_);

    cudaFuncSetAttribute(gemm_tc, cudaFuncAttributeMaxDynamicSharedMemorySize, GSMEM_TOT);
    dim3 gg(DM_ / 128, MROWS / 128);   // (4, 64)
    gemm_tc<<<gg, 256, GSMEM_TOT>>>(gah, gal, gwth + 0 * DM_ * DM_, gwtl + 0 * DM_ * DM_,
                                    bq, nullptr, gqh, gql);
    gemm_tc<<<gg, 256, GSMEM_TOT>>>(gah, gal, gwth + 1 * DM_ * DM_, gwtl + 1 * DM_ * DM_,
                                    bk, nullptr, gkh, gkl);
    gemm_tc<<<gg, 256, GSMEM_TOT>>>(gah, gal, gwth + 2 * DM_ * DM_, gwtl + 2 * DM_ * DM_,
                                    bv, nullptr, gvh, gvl);

    cudaMemsetAsync(gvm, 0, B_ * DM_ * sizeof(float));
    vmean_part<<<dim3(B_, 16), 256>>>();

    cudaFuncSetAttribute(attn_hmma, cudaFuncAttributeMaxDynamicSharedMemorySize, ASMEM);
    attn_hmma<<<dim3(S_ / QTA, H_, B_), 256, ASMEM>>>(xl);

    gemm_tc<<<gg, 256, GSMEM_TOT>>>(gah, gal, gwth + 3 * DM_ * DM_, gwtl + 3 * DM_ * DM_,
                                    bo, out, nullptr, nullptr);
}